// round 15
// baseline (speedup 1.0000x reference)
#include <cuda_runtime.h>
#include <cuda_fp16.h>
#include <cuda_bf16.h>

#define NN 50000
#define EE 400000
#define ET 450000   // EE + NN self loops
#define GG 1000
#define NPG 50
#define PREP_BLOCKS 1563

#define PDL_WAIT()   asm volatile("griddepcontrol.wait;" ::: "memory")
#define PDL_LAUNCH() asm volatile("griddepcontrol.launch_dependents;" ::: "memory")

// ---------------- static device scratch ----------------
static __device__ __align__(16) __half  g_xp1h[NN * 256];   // fp16 messages, layer 1
static __device__ __align__(16) __half  g_h1h[NN * 256];    // fp16 hidden, layer 1 out
static __device__ __align__(16) __half  g_xp2h[NN * 64];    // fp16 messages, layer 2
static __device__ __align__(16) float   g_asrc1[NN * 4];
// per-node record: [0..3] = adst1 (4 heads), [4..7] = den1 (4 heads) — one 32B sector
static __device__ __align__(32) float   g_nd1[NN * 8];
static __device__ float                 g_asrc2[NN];
static __device__ float                 g_adst2[NN];
static __device__ float                 g_tag[NN];
static __device__ float                 g_scnt[GG];         // solvent count per graph
// [0..3]=ue1, [4..7]=ve1, [8]=ue2, [9]=ve2, [10]=mean_ea0, [11]=mean_ea1
static __device__ float                 g_const[12];
// CSR by dst
static __device__ int                   g_cnt[NN];     // zero on entry; re-zeroed each run
static __device__ int                   g_row[NN + 1];
static __device__ int                   g_cur[NN];
static __device__ int                   g_part[128];
// packed per-edge payload: {src:int, ced:float, att01:half2, att23:half2}
static __device__ __align__(16) uint4   g_edge[ET];
static __device__ __align__(8) float2   g_eapart[PREP_BLOCKS];

// ---------------- bf16 split helpers ----------------
__device__ __forceinline__ void split_bf(float lo, float hi, unsigned& h, unsigned& l) {
    unsigned hh;
    asm("cvt.rn.bf16x2.f32 %0, %1, %2;" : "=r"(hh) : "f"(hi), "f"(lo));
    __nv_bfloat162 hb = *(__nv_bfloat162*)&hh;
    float rlo = lo - __bfloat162float(hb.x);
    float rhi = hi - __bfloat162float(hb.y);
    unsigned ll;
    asm("cvt.rn.bf16x2.f32 %0, %1, %2;" : "=r"(ll) : "f"(rhi), "f"(rlo));
    h = hh; l = ll;
}
__device__ __forceinline__ void mma_bf16(float* c, const unsigned* a, const unsigned* b) {
    asm volatile(
        "mma.sync.aligned.m16n8k16.row.col.f32.bf16.bf16.f32 "
        "{%0,%1,%2,%3}, {%4,%5,%6,%7}, {%8,%9}, {%0,%1,%2,%3};"
        : "+f"(c[0]), "+f"(c[1]), "+f"(c[2]), "+f"(c[3])
        : "r"(a[0]), "r"(a[1]), "r"(a[2]), "r"(a[3]), "r"(b[0]), "r"(b[1]));
}

// ---------------- prep: histogram + tags + zeroing + ea partial sums ----------------
__global__ void k_prep(const int* __restrict__ pm, const int* __restrict__ EI,
                       const float* __restrict__ EA, float* __restrict__ out) {
    __shared__ float2 sred[8];
    int tid = threadIdx.x;
    int e = blockIdx.x * 256 + tid;
    float2 v = make_float2(0.f, 0.f);
    if (e < EE) {
        atomicAdd(&g_cnt[EI[EE + e]], 1);
        v = ((const float2*)EA)[e];
    }
    if (e < NN) g_tag[e] = (e == NN - 1 || pm[e + 1] != pm[e]) ? 1.f : 0.f;
    if (e < NN * 4) g_nd1[(e >> 2) * 8 + 4 + (e & 3)] = 0.f;   // zero den slots
    if (e < GG) g_scnt[e] = 0.f;
    if (e < GG * 128) out[e] = 0.f;
    for (int o = 16; o; o >>= 1) {
        v.x += __shfl_xor_sync(0xFFFFFFFFu, v.x, o);
        v.y += __shfl_xor_sync(0xFFFFFFFFu, v.y, o);
    }
    if ((tid & 31) == 0) sred[tid >> 5] = v;
    __syncthreads();
    if (tid == 0) {
        float2 s = sred[0];
        for (int i = 1; i < 8; i++) { s.x += sred[i].x; s.y += sred[i].y; }
        g_eapart[blockIdx.x] = s;
    }
    PDL_LAUNCH();
}

// ---------------- scan1 (98 blocks) + const work (block 98) ----------------
__global__ void k_scan1(const float* __restrict__ We1, const float* __restrict__ atte1,
                        const float* __restrict__ We2, const float* __restrict__ atte2) {
    int t = threadIdx.x;
    PDL_WAIT();
    if (blockIdx.x == 98) {
        __shared__ float2 sred[16];
        if (t < 12) g_const[t] = 0.f;
        float2 v = make_float2(0.f, 0.f);
        for (int i = t; i < PREP_BLOCKS; i += 512) {
            float2 p = g_eapart[i];
            v.x += p.x; v.y += p.y;
        }
        for (int o = 16; o; o >>= 1) {
            v.x += __shfl_xor_sync(0xFFFFFFFFu, v.x, o);
            v.y += __shfl_xor_sync(0xFFFFFFFFu, v.y, o);
        }
        if ((t & 31) == 0) sred[t >> 5] = v;
        __syncthreads();
        if (t == 0) {
            float2 s = sred[0];
            for (int i = 1; i < 16; i++) { s.x += sred[i].x; s.y += sred[i].y; }
            g_const[10] = s.x * (1.f / EE);
            g_const[11] = s.y * (1.f / EE);
        }
        __syncthreads();
        if (t < 256) {
            int h = t >> 6;
            float a = atte1[t];
            atomicAdd(&g_const[h],     We1[t] * a);
            atomicAdd(&g_const[4 + h], We1[256 + t] * a);
            if (t < 64) {
                atomicAdd(&g_const[8], We2[t] * atte2[t]);
                atomicAdd(&g_const[9], We2[64 + t] * atte2[t]);
            }
        }
        PDL_LAUNCH();
        return;
    }
    __shared__ int sd[512];
    int i = blockIdx.x * 512 + t;
    int v = (i < NN) ? g_cnt[i] + 1 : 0;   // +1 self loop
    sd[t] = v; __syncthreads();
    for (int off = 1; off < 512; off <<= 1) {
        int x = (t >= off) ? sd[t - off] : 0;
        __syncthreads();
        sd[t] += x;
        __syncthreads();
    }
    if (i < NN) g_row[i + 1] = sd[t];
    if (t == 511) g_part[blockIdx.x] = sd[t];
    PDL_LAUNCH();
}

// ---------------- scan3: finalize row/cur, accumulate solvent counts ----------------
__global__ void k_scan3() {
    __shared__ int sp[98];
    int t = threadIdx.x;                   // 256
    PDL_WAIT();
    if (t < 98) sp[t] = g_part[t];
    __syncthreads();
    if (t == 0) {
        int run = 0;
        for (int i = 0; i < 98; i++) { int x = sp[i]; sp[i] = run; run += x; }
    }
    __syncthreads();
    int j = blockIdx.x * 256 + t;
    if (j <= NN) {
        int fr = (j == 0) ? 0 : (g_row[j] + sp[(j - 1) >> 9]);
        g_row[j] = fr;
        if (j < NN) {
            g_cur[j] = fr; g_cnt[j] = 0;   // re-zero cnt for next call
            float tg = g_tag[j];
            if (tg != 0.f) atomicAdd(&g_scnt[j / NPG], tg);
        }
    }
    PDL_LAUNCH();
}

// ---------------- GEMM1 (bf16x3 MMA): independent of the scan chain — no wait ----------------
__global__ __launch_bounds__(256) void k_gemm1(const float* __restrict__ A,
                                               const float* __restrict__ W,
                                               const float* __restrict__ atts,
                                               const float* __restrict__ attd,
                                               const int* __restrict__ pm) {
    __shared__ unsigned Ah[128 * 20], Al[128 * 20];
    __shared__ unsigned Bh[16 * 136], Bl[16 * 136];
    int tid = threadIdx.x;
    int wid = tid >> 5, lane = tid & 31;
    int warp_m = wid & 3, warp_n = wid >> 2;
    int q = lane >> 2, p = lane & 3;
    int m0 = blockIdx.x * 128, n0 = blockIdx.y * 128;
    float c[2][8][4];
#pragma unroll
    for (int i = 0; i < 2; i++)
#pragma unroll
        for (int j = 0; j < 8; j++)
#pragma unroll
            for (int k = 0; k < 4; k++) c[i][j][k] = 0.f;

    int arow = tid >> 1, ahalf = (tid & 1) * 16;
    int bkp = tid >> 4, bn8 = (tid & 15) * 8;

    for (int k0 = 0; k0 < 128; k0 += 32) {
        {
            bool ok = (m0 + arow) < NN;
            const float* ap = A + (long)(m0 + arow) * 128 + k0 + ahalf;
            unsigned hh[8], ll[8];
#pragma unroll
            for (int i = 0; i < 4; i++) {
                float4 v = ok ? *(const float4*)(ap + i * 4) : make_float4(0.f, 0.f, 0.f, 0.f);
                split_bf(v.x, v.y, hh[i * 2], ll[i * 2]);
                split_bf(v.z, v.w, hh[i * 2 + 1], ll[i * 2 + 1]);
            }
            int base = arow * 20 + (ahalf >> 1);
            *(uint4*)&Ah[base]     = make_uint4(hh[0], hh[1], hh[2], hh[3]);
            *(uint4*)&Ah[base + 4] = make_uint4(hh[4], hh[5], hh[6], hh[7]);
            *(uint4*)&Al[base]     = make_uint4(ll[0], ll[1], ll[2], ll[3]);
            *(uint4*)&Al[base + 4] = make_uint4(ll[4], ll[5], ll[6], ll[7]);
        }
        {
            const float* w0 = W + (long)(k0 + 2 * bkp) * 256 + n0 + bn8;
            const float* w1 = w0 + 256;
            float4 r0a = *(const float4*)w0, r0b = *(const float4*)(w0 + 4);
            float4 r1a = *(const float4*)w1, r1b = *(const float4*)(w1 + 4);
            unsigned hh[8], ll[8];
            split_bf(r0a.x, r1a.x, hh[0], ll[0]); split_bf(r0a.y, r1a.y, hh[1], ll[1]);
            split_bf(r0a.z, r1a.z, hh[2], ll[2]); split_bf(r0a.w, r1a.w, hh[3], ll[3]);
            split_bf(r0b.x, r1b.x, hh[4], ll[4]); split_bf(r0b.y, r1b.y, hh[5], ll[5]);
            split_bf(r0b.z, r1b.z, hh[6], ll[6]); split_bf(r0b.w, r1b.w, hh[7], ll[7]);
            int base = bkp * 136 + bn8;
            *(uint4*)&Bh[base]     = make_uint4(hh[0], hh[1], hh[2], hh[3]);
            *(uint4*)&Bh[base + 4] = make_uint4(hh[4], hh[5], hh[6], hh[7]);
            *(uint4*)&Bl[base]     = make_uint4(ll[0], ll[1], ll[2], ll[3]);
            *(uint4*)&Bl[base + 4] = make_uint4(ll[4], ll[5], ll[6], ll[7]);
        }
        __syncthreads();
#pragma unroll
        for (int kk = 0; kk < 2; kk++) {
            int kp = kk * 8 + p;
            unsigned ah[2][4], al[2][4], bh[8][2], bl[8][2];
#pragma unroll
            for (int i = 0; i < 2; i++) {
                int r0 = (warp_m * 32 + i * 16 + q) * 20;
                int r8 = r0 + 160;
                ah[i][0] = Ah[r0 + kp];     ah[i][1] = Ah[r8 + kp];
                ah[i][2] = Ah[r0 + kp + 4]; ah[i][3] = Ah[r8 + kp + 4];
                al[i][0] = Al[r0 + kp];     al[i][1] = Al[r8 + kp];
                al[i][2] = Al[r0 + kp + 4]; al[i][3] = Al[r8 + kp + 4];
            }
#pragma unroll
            for (int j = 0; j < 8; j++) {
                int n = warp_n * 64 + j * 8 + q;
                bh[j][0] = Bh[kp * 136 + n]; bh[j][1] = Bh[(kp + 4) * 136 + n];
                bl[j][0] = Bl[kp * 136 + n]; bl[j][1] = Bl[(kp + 4) * 136 + n];
            }
#pragma unroll
            for (int i = 0; i < 2; i++)
#pragma unroll
                for (int j = 0; j < 8; j++) {
                    mma_bf16(c[i][j], al[i], bh[j]);
                    mma_bf16(c[i][j], ah[i], bl[j]);
                    mma_bf16(c[i][j], ah[i], bh[j]);
                }
        }
        __syncthreads();
    }

    int head = blockIdx.y * 2 + warp_n;
    const float* asv = atts + head * 64;
    const float* adv = attd + head * 64;
    float ssum[2][2] = {}, dsum[2][2] = {};
#pragma unroll
    for (int i = 0; i < 2; i++) {
#pragma unroll
        for (int rb = 0; rb < 2; rb++) {
            int r = m0 + warp_m * 32 + i * 16 + q + rb * 8;
            bool ok = r < NN;
            float tg = ok ? ((r == NN - 1 || pm[r + 1] != pm[r]) ? 1.f : 0.f) : 0.f;
#pragma unroll
            for (int j = 0; j < 8; j++) {
                int cw = j * 8 + 2 * p;
                int col = n0 + warp_n * 64 + cw;
                float w0 = W[128 * 256 + col];
                float w1 = W[128 * 256 + col + 1];
                float v0 = c[i][j][rb * 2 + 0] + tg * w0;
                float v1 = c[i][j][rb * 2 + 1] + tg * w1;
                ssum[i][rb] += v0 * asv[cw] + v1 * asv[cw + 1];
                dsum[i][rb] += v0 * adv[cw] + v1 * adv[cw + 1];
                if (ok) ((__half2*)g_xp1h)[((long)r * 256 + col) >> 1] = __floats2half2_rn(v0, v1);
            }
        }
    }
#pragma unroll
    for (int i = 0; i < 2; i++)
#pragma unroll
        for (int rb = 0; rb < 2; rb++) {
            float s = ssum[i][rb], d = dsum[i][rb];
            s += __shfl_xor_sync(0xFFFFFFFFu, s, 1);
            s += __shfl_xor_sync(0xFFFFFFFFu, s, 2);
            d += __shfl_xor_sync(0xFFFFFFFFu, d, 1);
            d += __shfl_xor_sync(0xFFFFFFFFu, d, 2);
            if (p == 0) {
                int r = m0 + warp_m * 32 + i * 16 + q + rb * 8;
                if (r < NN) { g_asrc1[r * 4 + head] = s; g_nd1[r * 8 + head] = d; }
            }
        }
    PDL_LAUNCH();
}

// ---------------- scatter + fused layer-1 attention (packed 16B edge payload) ----------------
__global__ void k_scatter(const int* __restrict__ EI, const float* __restrict__ EA) {
    int e = blockIdx.x * blockDim.x + threadIdx.x;
    // prologue: pure-input loads overlap upstream tail
    int s = 0, d = 0; float2 ea = make_float2(0.f, 0.f);
    bool real = e < EE;
    if (real) {
        s = EI[e]; d = EI[EE + e];
        ea = ((const float2*)EA)[e];
    }
    PDL_WAIT();
    if (e >= ET) { PDL_LAUNCH(); return; }
    if (!real) {
        s = d = e - EE;
        ea.x = g_const[10]; ea.y = g_const[11];
    }
    int pos = atomicAdd(&g_cur[d], 1);
    float ced = ea.x * g_const[8] + ea.y * g_const[9];     // layer-2 edge logit term
    float4 as = *(const float4*)(g_asrc1 + s * 4);
    float4 ad = *(const float4*)(g_nd1 + d * 8);
    float a0 = as.x + ad.x + ea.x * g_const[0] + ea.y * g_const[4]; a0 = a0 >= 0.f ? a0 : 0.2f * a0;
    float a1 = as.y + ad.y + ea.x * g_const[1] + ea.y * g_const[5]; a1 = a1 >= 0.f ? a1 : 0.2f * a1;
    float a2 = as.z + ad.z + ea.x * g_const[2] + ea.y * g_const[6]; a2 = a2 >= 0.f ? a2 : 0.2f * a2;
    float a3 = as.w + ad.w + ea.x * g_const[3] + ea.y * g_const[7]; a3 = a3 >= 0.f ? a3 : 0.2f * a3;
    __half2 e01 = __floats2half2_rn(__expf(a0), __expf(a1));
    __half2 e23 = __floats2half2_rn(__expf(a2), __expf(a3));
    g_edge[pos] = make_uint4((unsigned)s, __float_as_uint(ced),
                             *(unsigned*)&e01, *(unsigned*)&e23);
    // den accumulates the fp16-rounded exps so each softmax still sums to exactly 1
    float2 r01 = __half22float2(e01), r23 = __half22float2(e23);
    atomicAdd((float4*)(g_nd1 + d * 8 + 4), make_float4(r01.x, r01.y, r23.x, r23.y));
    PDL_LAUNCH();
}

// ---------------- layer-1 aggregation: 1 warp/node, fp16 in/out, 2 edges/iter ----------------
__global__ __launch_bounds__(256) void k_agg1(const float* __restrict__ b1) {
    int w = (blockIdx.x * blockDim.x + threadIdx.x) >> 5;
    int lane = threadIdx.x & 31;
    PDL_WAIT();
    if (w >= NN) { PDL_LAUNCH(); return; }
    int s0 = g_row[w], e0 = g_row[w + 1];
    int head = lane >> 3;                  // 8 lanes per head
    float acc[8] = {};
    const uint4* X = (const uint4*)g_xp1h; // row = 32 uint4 (256 halfs)
    int j = s0;
    for (; j + 2 <= e0; j += 2) {
        uint4 eA = g_edge[j], eB = g_edge[j + 1];              // uniform
        uint4 hvA = X[(long)(int)eA.x * 32 + lane];
        uint4 hvB = X[(long)(int)eB.x * 32 + lane];
        float2 lA = __half22float2(*(__half2*)&eA.z), hA = __half22float2(*(__half2*)&eA.w);
        float2 lB = __half22float2(*(__half2*)&eB.z), hB = __half22float2(*(__half2*)&eB.w);
        float aA = head == 0 ? lA.x : head == 1 ? lA.y : head == 2 ? hA.x : hA.y;
        float aB = head == 0 ? lB.x : head == 1 ? lB.y : head == 2 ? hB.x : hB.y;
        float2 f;
        f = __half22float2(*(__half2*)&hvA.x); acc[0] += f.x * aA; acc[1] += f.y * aA;
        f = __half22float2(*(__half2*)&hvA.y); acc[2] += f.x * aA; acc[3] += f.y * aA;
        f = __half22float2(*(__half2*)&hvA.z); acc[4] += f.x * aA; acc[5] += f.y * aA;
        f = __half22float2(*(__half2*)&hvA.w); acc[6] += f.x * aA; acc[7] += f.y * aA;
        f = __half22float2(*(__half2*)&hvB.x); acc[0] += f.x * aB; acc[1] += f.y * aB;
        f = __half22float2(*(__half2*)&hvB.y); acc[2] += f.x * aB; acc[3] += f.y * aB;
        f = __half22float2(*(__half2*)&hvB.z); acc[4] += f.x * aB; acc[5] += f.y * aB;
        f = __half22float2(*(__half2*)&hvB.w); acc[6] += f.x * aB; acc[7] += f.y * aB;
    }
    if (j < e0) {
        uint4 eA = g_edge[j];
        uint4 hv = X[(long)(int)eA.x * 32 + lane];
        float2 lA = __half22float2(*(__half2*)&eA.z), hA = __half22float2(*(__half2*)&eA.w);
        float a = head == 0 ? lA.x : head == 1 ? lA.y : head == 2 ? hA.x : hA.y;
        float2 f;
        f = __half22float2(*(__half2*)&hv.x); acc[0] += f.x * a; acc[1] += f.y * a;
        f = __half22float2(*(__half2*)&hv.y); acc[2] += f.x * a; acc[3] += f.y * a;
        f = __half22float2(*(__half2*)&hv.z); acc[4] += f.x * a; acc[5] += f.y * a;
        f = __half22float2(*(__half2*)&hv.w); acc[6] += f.x * a; acc[7] += f.y * a;
    }
    float4 dv = *(const float4*)(g_nd1 + w * 8 + 4);
    float den = head == 0 ? dv.x : head == 1 ? dv.y : head == 2 ? dv.z : dv.w;
    float rd = 1.f / (den + 1e-16f);
    float4 ba = *(const float4*)(b1 + lane * 8);
    float4 bc = *(const float4*)(b1 + lane * 8 + 4);
    float o0 = fmaxf(acc[0] * rd + ba.x, 0.f), o1 = fmaxf(acc[1] * rd + ba.y, 0.f);
    float o2 = fmaxf(acc[2] * rd + ba.z, 0.f), o3 = fmaxf(acc[3] * rd + ba.w, 0.f);
    float o4 = fmaxf(acc[4] * rd + bc.x, 0.f), o5 = fmaxf(acc[5] * rd + bc.y, 0.f);
    float o6 = fmaxf(acc[6] * rd + bc.z, 0.f), o7 = fmaxf(acc[7] * rd + bc.w, 0.f);
    __half2 p0 = __floats2half2_rn(o0, o1), p1 = __floats2half2_rn(o2, o3);
    __half2 p2 = __floats2half2_rn(o4, o5), p3 = __floats2half2_rn(o6, o7);
    uint4 pk = make_uint4(*(unsigned*)&p0, *(unsigned*)&p1, *(unsigned*)&p2, *(unsigned*)&p3);
    *(uint4*)&g_h1h[(long)w * 256 + lane * 8] = pk;
    PDL_LAUNCH();
}

// ---------------- GEMM2 (bf16x3 MMA, fp16 A): xp2h = h1h@W2, fused a_src2/a_dst2 ----------------
__global__ __launch_bounds__(256) void k_gemm2(const float* __restrict__ W2,
                                               const float* __restrict__ atts,
                                               const float* __restrict__ attd) {
    __shared__ unsigned Ah[128 * 20], Al[128 * 20];
    __shared__ unsigned Bh[16 * 72], Bl[16 * 72];
    int tid = threadIdx.x;
    int wid = tid >> 5, lane = tid & 31;
    int q = lane >> 2, p = lane & 3;
    int m0 = blockIdx.x * 128;
    float c[8][4];
#pragma unroll
    for (int j = 0; j < 8; j++)
#pragma unroll
        for (int k = 0; k < 4; k++) c[j][k] = 0.f;

    int arow = tid >> 1, ahalf = (tid & 1) * 16;
    int bkp = tid >> 3, bn8 = (tid & 7) * 8;       // tid<128 loads B
    PDL_WAIT();

    for (int k0 = 0; k0 < 256; k0 += 32) {
        {
            bool ok = (m0 + arow) < NN;
            const __half* ap = g_h1h + (long)(m0 + arow) * 256 + k0 + ahalf;
            uint4 z = make_uint4(0u, 0u, 0u, 0u);
            uint4 u0 = ok ? *(const uint4*)ap : z;
            uint4 u1 = ok ? *(const uint4*)(ap + 8) : z;
            float f[16];
            float2 tt;
            tt = __half22float2(*(__half2*)&u0.x); f[0] = tt.x;  f[1] = tt.y;
            tt = __half22float2(*(__half2*)&u0.y); f[2] = tt.x;  f[3] = tt.y;
            tt = __half22float2(*(__half2*)&u0.z); f[4] = tt.x;  f[5] = tt.y;
            tt = __half22float2(*(__half2*)&u0.w); f[6] = tt.x;  f[7] = tt.y;
            tt = __half22float2(*(__half2*)&u1.x); f[8] = tt.x;  f[9] = tt.y;
            tt = __half22float2(*(__half2*)&u1.y); f[10] = tt.x; f[11] = tt.y;
            tt = __half22float2(*(__half2*)&u1.z); f[12] = tt.x; f[13] = tt.y;
            tt = __half22float2(*(__half2*)&u1.w); f[14] = tt.x; f[15] = tt.y;
            unsigned hh[8], ll[8];
#pragma unroll
            for (int i = 0; i < 8; i++) split_bf(f[2 * i], f[2 * i + 1], hh[i], ll[i]);
            int base = arow * 20 + (ahalf >> 1);
            *(uint4*)&Ah[base]     = make_uint4(hh[0], hh[1], hh[2], hh[3]);
            *(uint4*)&Ah[base + 4] = make_uint4(hh[4], hh[5], hh[6], hh[7]);
            *(uint4*)&Al[base]     = make_uint4(ll[0], ll[1], ll[2], ll[3]);
            *(uint4*)&Al[base + 4] = make_uint4(ll[4], ll[5], ll[6], ll[7]);
        }
        if (tid < 128) {
            const float* w0 = W2 + (long)(k0 + 2 * bkp) * 64 + bn8;
            const float* w1 = w0 + 64;
            float4 r0a = *(const float4*)w0, r0b = *(const float4*)(w0 + 4);
            float4 r1a = *(const float4*)w1, r1b = *(const float4*)(w1 + 4);
            unsigned hh[8], ll[8];
            split_bf(r0a.x, r1a.x, hh[0], ll[0]); split_bf(r0a.y, r1a.y, hh[1], ll[1]);
            split_bf(r0a.z, r1a.z, hh[2], ll[2]); split_bf(r0a.w, r1a.w, hh[3], ll[3]);
            split_bf(r0b.x, r1b.x, hh[4], ll[4]); split_bf(r0b.y, r1b.y, hh[5], ll[5]);
            split_bf(r0b.z, r1b.z, hh[6], ll[6]); split_bf(r0b.w, r1b.w, hh[7], ll[7]);
            int base = bkp * 72 + bn8;
            *(uint4*)&Bh[base]     = make_uint4(hh[0], hh[1], hh[2], hh[3]);
            *(uint4*)&Bh[base + 4] = make_uint4(hh[4], hh[5], hh[6], hh[7]);
            *(uint4*)&Bl[base]     = make_uint4(ll[0], ll[1], ll[2], ll[3]);
            *(uint4*)&Bl[base + 4] = make_uint4(ll[4], ll[5], ll[6], ll[7]);
        }
        __syncthreads();
#pragma unroll
        for (int kk = 0; kk < 2; kk++) {
            int kp = kk * 8 + p;
            unsigned ah[4], al[4], bh[8][2], bl[8][2];
            int r0 = (wid * 16 + q) * 20;
            int r8 = r0 + 160;
            ah[0] = Ah[r0 + kp];     ah[1] = Ah[r8 + kp];
            ah[2] = Ah[r0 + kp + 4]; ah[3] = Ah[r8 + kp + 4];
            al[0] = Al[r0 + kp];     al[1] = Al[r8 + kp];
            al[2] = Al[r0 + kp + 4]; al[3] = Al[r8 + kp + 4];
#pragma unroll
            for (int j = 0; j < 8; j++) {
                int n = j * 8 + q;
                bh[j][0] = Bh[kp * 72 + n]; bh[j][1] = Bh[(kp + 4) * 72 + n];
                bl[j][0] = Bl[kp * 72 + n]; bl[j][1] = Bl[(kp + 4) * 72 + n];
            }
#pragma unroll
            for (int j = 0; j < 8; j++) {
                mma_bf16(c[j], al, bh[j]);
                mma_bf16(c[j], ah, bl[j]);
                mma_bf16(c[j], ah, bh[j]);
            }
        }
        __syncthreads();
    }

    float ssum[2] = {}, dsum[2] = {};
#pragma unroll
    for (int rb = 0; rb < 2; rb++) {
        int r = m0 + wid * 16 + q + rb * 8;
        bool ok = r < NN;
#pragma unroll
        for (int j = 0; j < 8; j++) {
            int cw = j * 8 + 2 * p;
            float v0 = c[j][rb * 2 + 0];
            float v1 = c[j][rb * 2 + 1];
            ssum[rb] += v0 * atts[cw] + v1 * atts[cw + 1];
            dsum[rb] += v0 * attd[cw] + v1 * attd[cw + 1];
            if (ok) ((__half2*)g_xp2h)[((long)r * 64 + cw) >> 1] = __floats2half2_rn(v0, v1);
        }
    }
#pragma unroll
    for (int rb = 0; rb < 2; rb++) {
        float s = ssum[rb], d = dsum[rb];
        s += __shfl_xor_sync(0xFFFFFFFFu, s, 1);
        s += __shfl_xor_sync(0xFFFFFFFFu, s, 2);
        d += __shfl_xor_sync(0xFFFFFFFFu, d, 1);
        d += __shfl_xor_sync(0xFFFFFFFFu, d, 2);
        if (p == 0) {
            int r = m0 + wid * 16 + q + rb * 8;
            if (r < NN) { g_asrc2[r] = s; g_adst2[r] = d; }
        }
    }
    PDL_LAUNCH();
}

// ---------------- layer-2: fused softmax + aggregation + pooling (warp/node) ----------------
__global__ __launch_bounds__(256) void k_agg2(const float* __restrict__ b2,
                                              float* __restrict__ out) {
    int w = (blockIdx.x * blockDim.x + threadIdx.x) >> 5;
    int lane = threadIdx.x & 31;
    PDL_WAIT();
    if (w >= NN) return;
    int s0 = g_row[w], e0 = g_row[w + 1];
    // --- softmax (max-free; logits bounded) across lanes, up to 96 edges ---
    float ad = g_adst2[w];
    float att_l[3];
    float den = 0.f;
#pragma unroll
    for (int it = 0; it < 3; it++) {
        int j = s0 + it * 32 + lane;
        float ex = 0.f;
        if (j < e0) {
            uint4 ej = g_edge[j];
            float a = g_asrc2[(int)ej.x] + ad + __uint_as_float(ej.y);
            a = a >= 0.f ? a : 0.2f * a;
            ex = __expf(a);
        }
        att_l[it] = ex;
        den += ex;
    }
    for (int o = 16; o; o >>= 1) den += __shfl_xor_sync(0xFFFFFFFFu, den, o);
    float rd = 1.f / (den + 1e-16f);
    // --- gather: 4 edge-slots x 8 lanes ---
    int g8 = lane >> 3, sl = lane & 7;
    float acc[8] = {};
    const uint4* X = (const uint4*)g_xp2h; // row = 8 uint4 (64 halfs)
    for (int base = s0; base < e0; base += 4) {
        int j = base + g8;
        int rel = j - s0;
        int src = (j < e0) ? (int)g_edge[j].x : 0;
        float a0 = __shfl_sync(0xFFFFFFFFu, att_l[0], rel & 31);
        float a1 = __shfl_sync(0xFFFFFFFFu, att_l[1], rel & 31);
        float a2 = __shfl_sync(0xFFFFFFFFu, att_l[2], rel & 31);
        if (j < e0) {
            float a = (rel < 32) ? a0 : ((rel < 64) ? a1 : a2);
            uint4 hv = X[(long)src * 8 + sl];
            float2 f0 = __half22float2(*(__half2*)&hv.x);
            float2 f1 = __half22float2(*(__half2*)&hv.y);
            float2 f2 = __half22float2(*(__half2*)&hv.z);
            float2 f3 = __half22float2(*(__half2*)&hv.w);
            acc[0] += f0.x * a; acc[1] += f0.y * a; acc[2] += f1.x * a; acc[3] += f1.y * a;
            acc[4] += f2.x * a; acc[5] += f2.y * a; acc[6] += f3.x * a; acc[7] += f3.y * a;
        }
    }
#pragma unroll
    for (int k = 0; k < 8; k++) {
        acc[k] += __shfl_xor_sync(0xFFFFFFFFu, acc[k], 8);
        acc[k] += __shfl_xor_sync(0xFFFFFFFFu, acc[k], 16);
    }
    if (lane < 8) {
        float4 ba = *(const float4*)(b2 + sl * 8);
        float4 bc = *(const float4*)(b2 + sl * 8 + 4);
        int g = w / NPG;
        float t = g_tag[w];
        float sc = g_scnt[g];
        float wgt = (t > 0.5f) ? (1.f / fmaxf(sc, 1.f)) : (1.f / fmaxf((float)NPG - sc, 1.f));
        int off = g * 128 + (t > 0.5f ? 64 : 0) + sl * 8;
        float4 o1 = make_float4((acc[0] * rd + ba.x) * wgt, (acc[1] * rd + ba.y) * wgt,
                                (acc[2] * rd + ba.z) * wgt, (acc[3] * rd + ba.w) * wgt);
        float4 o2 = make_float4((acc[4] * rd + bc.x) * wgt, (acc[5] * rd + bc.y) * wgt,
                                (acc[6] * rd + bc.z) * wgt, (acc[7] * rd + bc.w) * wgt);
        atomicAdd((float4*)(out + off), o1);
        atomicAdd((float4*)(out + off + 4), o2);
    }
}

// ---------------- PDL launch helper ----------------
static inline void pdl_launch(const void* fn, dim3 gd, dim3 bd, void** args) {
    cudaLaunchConfig_t cfg = {};
    cfg.gridDim = gd;
    cfg.blockDim = bd;
    cfg.dynamicSmemBytes = 0;
    cfg.stream = 0;
    cudaLaunchAttribute at;
    at.id = cudaLaunchAttributeProgrammaticStreamSerialization;
    at.val.programmaticStreamSerializationAllowed = 1;
    cfg.attrs = &at;
    cfg.numAttrs = 1;
    cudaLaunchKernelExC(&cfg, fn, args);
}

// ---------------- launch ----------------
extern "C" void kernel_launch(void* const* d_in, const int* in_sizes, int n_in,
                              void* d_out, int out_size) {
    const float* nf    = (const float*)d_in[0];
    const int*   ei    = (const int*)d_in[1];
    const float* ea    = (const float*)d_in[2];
    const int*   pm    = (const int*)d_in[3];
    const float* W1    = (const float*)d_in[4];
    const float* We1   = (const float*)d_in[5];
    const float* atts1 = (const float*)d_in[6];
    const float* attd1 = (const float*)d_in[7];
    const float* atte1 = (const float*)d_in[8];
    const float* b1    = (const float*)d_in[9];
    const float* W2    = (const float*)d_in[10];
    const float* We2   = (const float*)d_in[11];
    const float* atts2 = (const float*)d_in[12];
    const float* attd2 = (const float*)d_in[13];
    const float* atte2 = (const float*)d_in[14];
    const float* b2    = (const float*)d_in[15];
    float* out = (float*)d_out;

    k_prep<<<PREP_BLOCKS, 256>>>(pm, ei, ea, out);
    {
        void* a[] = {(void*)&We1, (void*)&atte1, (void*)&We2, (void*)&atte2};
        pdl_launch((const void*)k_scan1, dim3(99), dim3(512), a);
    }
    {
        void* a[] = {};
        pdl_launch((const void*)k_scan3, dim3((NN + 1 + 255) / 256), dim3(256), a);
    }
    {
        void* a[] = {(void*)&nf, (void*)&W1, (void*)&atts1, (void*)&attd1, (void*)&pm};
        pdl_launch((const void*)k_gemm1, dim3((NN + 127) / 128, 2), dim3(256), a);
    }
    {
        void* a[] = {(void*)&ei, (void*)&ea};
        pdl_launch((const void*)k_scatter, dim3((ET + 255) / 256), dim3(256), a);
    }
    {
        void* a[] = {(void*)&b1};
        pdl_launch((const void*)k_agg1, dim3((NN * 32 + 255) / 256), dim3(256), a);
    }
    {
        void* a[] = {(void*)&W2, (void*)&atts2, (void*)&attd2};
        pdl_launch((const void*)k_gemm2, dim3((NN + 127) / 128), dim3(256), a);
    }
    {
        void* a[] = {(void*)&b2, (void*)&out};
        pdl_launch((const void*)k_agg2, dim3((NN * 32 + 255) / 256), dim3(256), a);
    }
}

// round 16
// speedup vs baseline: 1.1636x; 1.1636x over previous
#include <cuda_runtime.h>
#include <cuda_fp16.h>

#define NN 50000
#define EE 400000
#define ET 450000   // EE + NN self loops
#define GG 1000
#define NPG 50
#define PREP_BLOCKS 1563

#define PDL_WAIT()   asm volatile("griddepcontrol.wait;" ::: "memory")
#define PDL_LAUNCH() asm volatile("griddepcontrol.launch_dependents;" ::: "memory")

// ---------------- static device scratch ----------------
static __device__ __align__(16) __half  g_xp1h[NN * 256];   // fp16 messages, layer 1
static __device__ __align__(16) __half  g_h1h[NN * 256];    // fp16 hidden, layer 1 out
static __device__ __align__(16) __half  g_xp2h[NN * 64];    // fp16 messages, layer 2
static __device__ __align__(16) float   g_asrc1[NN * 4];
// per-node record: [0..3] = adst1 (4 heads), [4..7] = den1 (4 heads) — one 32B sector
static __device__ __align__(32) float   g_nd1[NN * 8];
static __device__ float                 g_asrc2[NN];
static __device__ float                 g_adst2[NN];
static __device__ float                 g_tag[NN];
static __device__ float                 g_scnt[GG];         // solvent count per graph
// [0..3]=ue1, [4..7]=ve1, [8]=ue2, [9]=ve2, [10]=mean_ea0, [11]=mean_ea1
static __device__ float                 g_const[12];
// CSR by dst
static __device__ int                   g_cnt[NN];     // zero on entry; re-zeroed each run
static __device__ int                   g_row[NN + 1];
static __device__ int                   g_cur[NN];
static __device__ int                   g_part[128];
// packed per-edge payload: {src:int, ced:float, att01:half2, att23:half2}
static __device__ __align__(16) uint4   g_edge[ET];
static __device__ __align__(8) float2   g_eapart[PREP_BLOCKS];

// ---------------- fp16 helpers ----------------
__device__ __forceinline__ unsigned pack_h2(float lo, float hi) {
    __half2 h = __floats2half2_rn(lo, hi);
    return *(unsigned*)&h;
}
__device__ __forceinline__ void mma_fp16(float* c, const unsigned* a, const unsigned* b) {
    asm volatile(
        "mma.sync.aligned.m16n8k16.row.col.f32.f16.f16.f32 "
        "{%0,%1,%2,%3}, {%4,%5,%6,%7}, {%8,%9}, {%0,%1,%2,%3};"
        : "+f"(c[0]), "+f"(c[1]), "+f"(c[2]), "+f"(c[3])
        : "r"(a[0]), "r"(a[1]), "r"(a[2]), "r"(a[3]), "r"(b[0]), "r"(b[1]));
}

// ---------------- prep: histogram + tags + zeroing + ea partial sums ----------------
__global__ void k_prep(const int* __restrict__ pm, const int* __restrict__ EI,
                       const float* __restrict__ EA, float* __restrict__ out) {
    __shared__ float2 sred[8];
    int tid = threadIdx.x;
    int e = blockIdx.x * 256 + tid;
    float2 v = make_float2(0.f, 0.f);
    if (e < EE) {
        atomicAdd(&g_cnt[EI[EE + e]], 1);
        v = ((const float2*)EA)[e];
    }
    if (e < NN) g_tag[e] = (e == NN - 1 || pm[e + 1] != pm[e]) ? 1.f : 0.f;
    if (e < NN * 4) g_nd1[(e >> 2) * 8 + 4 + (e & 3)] = 0.f;   // zero den slots
    if (e < GG) g_scnt[e] = 0.f;
    if (e < GG * 128) out[e] = 0.f;
    for (int o = 16; o; o >>= 1) {
        v.x += __shfl_xor_sync(0xFFFFFFFFu, v.x, o);
        v.y += __shfl_xor_sync(0xFFFFFFFFu, v.y, o);
    }
    if ((tid & 31) == 0) sred[tid >> 5] = v;
    __syncthreads();
    if (tid == 0) {
        float2 s = sred[0];
        for (int i = 1; i < 8; i++) { s.x += sred[i].x; s.y += sred[i].y; }
        g_eapart[blockIdx.x] = s;
    }
    PDL_LAUNCH();
}

// ---------------- scan1 (98 blocks) + const work (block 98) ----------------
__global__ void k_scan1(const float* __restrict__ We1, const float* __restrict__ atte1,
                        const float* __restrict__ We2, const float* __restrict__ atte2) {
    int t = threadIdx.x;
    PDL_WAIT();
    if (blockIdx.x == 98) {
        __shared__ float2 sred[16];
        if (t < 12) g_const[t] = 0.f;
        float2 v = make_float2(0.f, 0.f);
        for (int i = t; i < PREP_BLOCKS; i += 512) {
            float2 p = g_eapart[i];
            v.x += p.x; v.y += p.y;
        }
        for (int o = 16; o; o >>= 1) {
            v.x += __shfl_xor_sync(0xFFFFFFFFu, v.x, o);
            v.y += __shfl_xor_sync(0xFFFFFFFFu, v.y, o);
        }
        if ((t & 31) == 0) sred[t >> 5] = v;
        __syncthreads();
        if (t == 0) {
            float2 s = sred[0];
            for (int i = 1; i < 16; i++) { s.x += sred[i].x; s.y += sred[i].y; }
            g_const[10] = s.x * (1.f / EE);
            g_const[11] = s.y * (1.f / EE);
        }
        __syncthreads();
        if (t < 256) {
            int h = t >> 6;
            float a = atte1[t];
            atomicAdd(&g_const[h],     We1[t] * a);
            atomicAdd(&g_const[4 + h], We1[256 + t] * a);
            if (t < 64) {
                atomicAdd(&g_const[8], We2[t] * atte2[t]);
                atomicAdd(&g_const[9], We2[64 + t] * atte2[t]);
            }
        }
        PDL_LAUNCH();
        return;
    }
    __shared__ int sd[512];
    int i = blockIdx.x * 512 + t;
    int v = (i < NN) ? g_cnt[i] + 1 : 0;   // +1 self loop
    sd[t] = v; __syncthreads();
    for (int off = 1; off < 512; off <<= 1) {
        int x = (t >= off) ? sd[t - off] : 0;
        __syncthreads();
        sd[t] += x;
        __syncthreads();
    }
    if (i < NN) g_row[i + 1] = sd[t];
    if (t == 511) g_part[blockIdx.x] = sd[t];
    PDL_LAUNCH();
}

// ---------------- scan3: finalize row/cur, accumulate solvent counts ----------------
__global__ void k_scan3() {
    __shared__ int sp[98];
    int t = threadIdx.x;                   // 256
    PDL_WAIT();
    if (t < 98) sp[t] = g_part[t];
    __syncthreads();
    if (t == 0) {
        int run = 0;
        for (int i = 0; i < 98; i++) { int x = sp[i]; sp[i] = run; run += x; }
    }
    __syncthreads();
    int j = blockIdx.x * 256 + t;
    if (j <= NN) {
        int fr = (j == 0) ? 0 : (g_row[j] + sp[(j - 1) >> 9]);
        g_row[j] = fr;
        if (j < NN) {
            g_cur[j] = fr; g_cnt[j] = 0;   // re-zero cnt for next call
            float tg = g_tag[j];
            if (tg != 0.f) atomicAdd(&g_scnt[j / NPG], tg);
        }
    }
    PDL_LAUNCH();
}

// ---------------- GEMM1 (fp16 MMA): xp1h = [NF|tag]@W1, fused a_src/a_dst ----------------
__global__ __launch_bounds__(256) void k_gemm1(const float* __restrict__ A,
                                               const float* __restrict__ W,
                                               const float* __restrict__ atts,
                                               const float* __restrict__ attd,
                                               const int* __restrict__ pm) {
    __shared__ unsigned Ah[128 * 20];      // k-pairs, pitch 20
    __shared__ unsigned Bh[16 * 136];      // k-pair rows x n, pitch 136
    int tid = threadIdx.x;
    int wid = tid >> 5, lane = tid & 31;
    int warp_m = wid & 3, warp_n = wid >> 2;
    int q = lane >> 2, p = lane & 3;
    int m0 = blockIdx.x * 128, n0 = blockIdx.y * 128;
    float c[2][8][4];
#pragma unroll
    for (int i = 0; i < 2; i++)
#pragma unroll
        for (int j = 0; j < 8; j++)
#pragma unroll
            for (int k = 0; k < 4; k++) c[i][j][k] = 0.f;

    int arow = tid >> 1, ahalf = (tid & 1) * 16;
    int bkp = tid >> 4, bn8 = (tid & 15) * 8;

    for (int k0 = 0; k0 < 128; k0 += 32) {
        {
            bool ok = (m0 + arow) < NN;
            const float* ap = A + (long)(m0 + arow) * 128 + k0 + ahalf;
            unsigned hh[8];
#pragma unroll
            for (int i = 0; i < 4; i++) {
                float4 v = ok ? *(const float4*)(ap + i * 4) : make_float4(0.f, 0.f, 0.f, 0.f);
                hh[i * 2]     = pack_h2(v.x, v.y);
                hh[i * 2 + 1] = pack_h2(v.z, v.w);
            }
            int base = arow * 20 + (ahalf >> 1);
            *(uint4*)&Ah[base]     = make_uint4(hh[0], hh[1], hh[2], hh[3]);
            *(uint4*)&Ah[base + 4] = make_uint4(hh[4], hh[5], hh[6], hh[7]);
        }
        {
            const float* w0 = W + (long)(k0 + 2 * bkp) * 256 + n0 + bn8;
            const float* w1 = w0 + 256;
            float4 r0a = *(const float4*)w0, r0b = *(const float4*)(w0 + 4);
            float4 r1a = *(const float4*)w1, r1b = *(const float4*)(w1 + 4);
            unsigned hh[8];
            hh[0] = pack_h2(r0a.x, r1a.x); hh[1] = pack_h2(r0a.y, r1a.y);
            hh[2] = pack_h2(r0a.z, r1a.z); hh[3] = pack_h2(r0a.w, r1a.w);
            hh[4] = pack_h2(r0b.x, r1b.x); hh[5] = pack_h2(r0b.y, r1b.y);
            hh[6] = pack_h2(r0b.z, r1b.z); hh[7] = pack_h2(r0b.w, r1b.w);
            int base = bkp * 136 + bn8;
            *(uint4*)&Bh[base]     = make_uint4(hh[0], hh[1], hh[2], hh[3]);
            *(uint4*)&Bh[base + 4] = make_uint4(hh[4], hh[5], hh[6], hh[7]);
        }
        __syncthreads();
#pragma unroll
        for (int kk = 0; kk < 2; kk++) {
            int kp = kk * 8 + p;
            unsigned ah[2][4], bh[8][2];
#pragma unroll
            for (int i = 0; i < 2; i++) {
                int r0 = (warp_m * 32 + i * 16 + q) * 20;
                int r8 = r0 + 160;
                ah[i][0] = Ah[r0 + kp];     ah[i][1] = Ah[r8 + kp];
                ah[i][2] = Ah[r0 + kp + 4]; ah[i][3] = Ah[r8 + kp + 4];
            }
#pragma unroll
            for (int j = 0; j < 8; j++) {
                int n = warp_n * 64 + j * 8 + q;
                bh[j][0] = Bh[kp * 136 + n]; bh[j][1] = Bh[(kp + 4) * 136 + n];
            }
#pragma unroll
            for (int i = 0; i < 2; i++)
#pragma unroll
                for (int j = 0; j < 8; j++) mma_fp16(c[i][j], ah[i], bh[j]);
        }
        __syncthreads();
    }

    int head = blockIdx.y * 2 + warp_n;
    const float* asv = atts + head * 64;
    const float* adv = attd + head * 64;
    float ssum[2][2] = {}, dsum[2][2] = {};
#pragma unroll
    for (int i = 0; i < 2; i++) {
#pragma unroll
        for (int rb = 0; rb < 2; rb++) {
            int r = m0 + warp_m * 32 + i * 16 + q + rb * 8;
            bool ok = r < NN;
            float tg = ok ? ((r == NN - 1 || pm[r + 1] != pm[r]) ? 1.f : 0.f) : 0.f;
#pragma unroll
            for (int j = 0; j < 8; j++) {
                int cw = j * 8 + 2 * p;
                int col = n0 + warp_n * 64 + cw;
                float w0 = W[128 * 256 + col];
                float w1 = W[128 * 256 + col + 1];
                float v0 = c[i][j][rb * 2 + 0] + tg * w0;
                float v1 = c[i][j][rb * 2 + 1] + tg * w1;
                ssum[i][rb] += v0 * asv[cw] + v1 * asv[cw + 1];
                dsum[i][rb] += v0 * adv[cw] + v1 * adv[cw + 1];
                if (ok) ((__half2*)g_xp1h)[((long)r * 256 + col) >> 1] = __floats2half2_rn(v0, v1);
            }
        }
    }
#pragma unroll
    for (int i = 0; i < 2; i++)
#pragma unroll
        for (int rb = 0; rb < 2; rb++) {
            float s = ssum[i][rb], d = dsum[i][rb];
            s += __shfl_xor_sync(0xFFFFFFFFu, s, 1);
            s += __shfl_xor_sync(0xFFFFFFFFu, s, 2);
            d += __shfl_xor_sync(0xFFFFFFFFu, d, 1);
            d += __shfl_xor_sync(0xFFFFFFFFu, d, 2);
            if (p == 0) {
                int r = m0 + warp_m * 32 + i * 16 + q + rb * 8;
                if (r < NN) { g_asrc1[r * 4 + head] = s; g_nd1[r * 8 + head] = d; }
            }
        }
    PDL_LAUNCH();
}

// ---------------- scatter + fused layer-1 attention (packed 16B edge payload) ----------------
__global__ void k_scatter(const int* __restrict__ EI, const float* __restrict__ EA) {
    int e = blockIdx.x * blockDim.x + threadIdx.x;
    int s = 0, d = 0; float2 ea = make_float2(0.f, 0.f);
    bool real = e < EE;
    if (real) {
        s = EI[e]; d = EI[EE + e];
        ea = ((const float2*)EA)[e];
    }
    PDL_WAIT();
    if (e >= ET) { PDL_LAUNCH(); return; }
    if (!real) {
        s = d = e - EE;
        ea.x = g_const[10]; ea.y = g_const[11];
    }
    int pos = atomicAdd(&g_cur[d], 1);
    float ced = ea.x * g_const[8] + ea.y * g_const[9];     // layer-2 edge logit term
    float4 as = *(const float4*)(g_asrc1 + s * 4);
    float4 ad = *(const float4*)(g_nd1 + d * 8);
    float a0 = as.x + ad.x + ea.x * g_const[0] + ea.y * g_const[4]; a0 = a0 >= 0.f ? a0 : 0.2f * a0;
    float a1 = as.y + ad.y + ea.x * g_const[1] + ea.y * g_const[5]; a1 = a1 >= 0.f ? a1 : 0.2f * a1;
    float a2 = as.z + ad.z + ea.x * g_const[2] + ea.y * g_const[6]; a2 = a2 >= 0.f ? a2 : 0.2f * a2;
    float a3 = as.w + ad.w + ea.x * g_const[3] + ea.y * g_const[7]; a3 = a3 >= 0.f ? a3 : 0.2f * a3;
    __half2 e01 = __floats2half2_rn(__expf(a0), __expf(a1));
    __half2 e23 = __floats2half2_rn(__expf(a2), __expf(a3));
    g_edge[pos] = make_uint4((unsigned)s, __float_as_uint(ced),
                             *(unsigned*)&e01, *(unsigned*)&e23);
    // den accumulates the fp16-rounded exps so each softmax still sums to exactly 1
    float2 r01 = __half22float2(e01), r23 = __half22float2(e23);
    atomicAdd((float4*)(g_nd1 + d * 8 + 4), make_float4(r01.x, r01.y, r23.x, r23.y));
    PDL_LAUNCH();
}

// ---------------- layer-1 aggregation: 1 warp/node, fp16 in/out, 2 edges/iter ----------------
__global__ __launch_bounds__(256) void k_agg1(const float* __restrict__ b1) {
    int w = (blockIdx.x * blockDim.x + threadIdx.x) >> 5;
    int lane = threadIdx.x & 31;
    PDL_WAIT();
    if (w >= NN) { PDL_LAUNCH(); return; }
    int s0 = g_row[w], e0 = g_row[w + 1];
    int head = lane >> 3;                  // 8 lanes per head
    float acc[8] = {};
    const uint4* X = (const uint4*)g_xp1h; // row = 32 uint4 (256 halfs)
    int j = s0;
    for (; j + 2 <= e0; j += 2) {
        uint4 eA = g_edge[j], eB = g_edge[j + 1];              // uniform
        uint4 hvA = X[(long)(int)eA.x * 32 + lane];
        uint4 hvB = X[(long)(int)eB.x * 32 + lane];
        float2 lA = __half22float2(*(__half2*)&eA.z), hA = __half22float2(*(__half2*)&eA.w);
        float2 lB = __half22float2(*(__half2*)&eB.z), hB = __half22float2(*(__half2*)&eB.w);
        float aA = head == 0 ? lA.x : head == 1 ? lA.y : head == 2 ? hA.x : hA.y;
        float aB = head == 0 ? lB.x : head == 1 ? lB.y : head == 2 ? hB.x : hB.y;
        float2 f;
        f = __half22float2(*(__half2*)&hvA.x); acc[0] += f.x * aA; acc[1] += f.y * aA;
        f = __half22float2(*(__half2*)&hvA.y); acc[2] += f.x * aA; acc[3] += f.y * aA;
        f = __half22float2(*(__half2*)&hvA.z); acc[4] += f.x * aA; acc[5] += f.y * aA;
        f = __half22float2(*(__half2*)&hvA.w); acc[6] += f.x * aA; acc[7] += f.y * aA;
        f = __half22float2(*(__half2*)&hvB.x); acc[0] += f.x * aB; acc[1] += f.y * aB;
        f = __half22float2(*(__half2*)&hvB.y); acc[2] += f.x * aB; acc[3] += f.y * aB;
        f = __half22float2(*(__half2*)&hvB.z); acc[4] += f.x * aB; acc[5] += f.y * aB;
        f = __half22float2(*(__half2*)&hvB.w); acc[6] += f.x * aB; acc[7] += f.y * aB;
    }
    if (j < e0) {
        uint4 eA = g_edge[j];
        uint4 hv = X[(long)(int)eA.x * 32 + lane];
        float2 lA = __half22float2(*(__half2*)&eA.z), hA = __half22float2(*(__half2*)&eA.w);
        float a = head == 0 ? lA.x : head == 1 ? lA.y : head == 2 ? hA.x : hA.y;
        float2 f;
        f = __half22float2(*(__half2*)&hv.x); acc[0] += f.x * a; acc[1] += f.y * a;
        f = __half22float2(*(__half2*)&hv.y); acc[2] += f.x * a; acc[3] += f.y * a;
        f = __half22float2(*(__half2*)&hv.z); acc[4] += f.x * a; acc[5] += f.y * a;
        f = __half22float2(*(__half2*)&hv.w); acc[6] += f.x * a; acc[7] += f.y * a;
    }
    float4 dv = *(const float4*)(g_nd1 + w * 8 + 4);
    float den = head == 0 ? dv.x : head == 1 ? dv.y : head == 2 ? dv.z : dv.w;
    float rd = 1.f / (den + 1e-16f);
    float4 ba = *(const float4*)(b1 + lane * 8);
    float4 bc = *(const float4*)(b1 + lane * 8 + 4);
    float o0 = fmaxf(acc[0] * rd + ba.x, 0.f), o1 = fmaxf(acc[1] * rd + ba.y, 0.f);
    float o2 = fmaxf(acc[2] * rd + ba.z, 0.f), o3 = fmaxf(acc[3] * rd + ba.w, 0.f);
    float o4 = fmaxf(acc[4] * rd + bc.x, 0.f), o5 = fmaxf(acc[5] * rd + bc.y, 0.f);
    float o6 = fmaxf(acc[6] * rd + bc.z, 0.f), o7 = fmaxf(acc[7] * rd + bc.w, 0.f);
    __half2 p0 = __floats2half2_rn(o0, o1), p1 = __floats2half2_rn(o2, o3);
    __half2 p2 = __floats2half2_rn(o4, o5), p3 = __floats2half2_rn(o6, o7);
    uint4 pk = make_uint4(*(unsigned*)&p0, *(unsigned*)&p1, *(unsigned*)&p2, *(unsigned*)&p3);
    *(uint4*)&g_h1h[(long)w * 256 + lane * 8] = pk;
    PDL_LAUNCH();
}

// ---------------- GEMM2 (fp16 MMA, fp16 A direct copy): xp2h = h1h@W2 ----------------
__global__ __launch_bounds__(256) void k_gemm2(const float* __restrict__ W2,
                                               const float* __restrict__ atts,
                                               const float* __restrict__ attd) {
    __shared__ unsigned Ah[128 * 20];
    __shared__ unsigned Bh[16 * 72];
    int tid = threadIdx.x;
    int wid = tid >> 5, lane = tid & 31;
    int q = lane >> 2, p = lane & 3;
    int m0 = blockIdx.x * 128;
    float c[8][4];
#pragma unroll
    for (int j = 0; j < 8; j++)
#pragma unroll
        for (int k = 0; k < 4; k++) c[j][k] = 0.f;

    int arow = tid >> 1, ahalf = (tid & 1) * 16;
    int bkp = tid >> 3, bn8 = (tid & 7) * 8;       // tid<128 loads B
    PDL_WAIT();

    for (int k0 = 0; k0 < 256; k0 += 32) {
        {
            bool ok = (m0 + arow) < NN;
            const __half* ap = g_h1h + (long)(m0 + arow) * 256 + k0 + ahalf;
            uint4 z = make_uint4(0u, 0u, 0u, 0u);
            uint4 u0 = ok ? *(const uint4*)ap : z;
            uint4 u1 = ok ? *(const uint4*)(ap + 8) : z;
            int base = arow * 20 + (ahalf >> 1);
            *(uint4*)&Ah[base]     = u0;           // halfs already (k even, k odd) packed
            *(uint4*)&Ah[base + 4] = u1;
        }
        if (tid < 128) {
            const float* w0 = W2 + (long)(k0 + 2 * bkp) * 64 + bn8;
            const float* w1 = w0 + 64;
            float4 r0a = *(const float4*)w0, r0b = *(const float4*)(w0 + 4);
            float4 r1a = *(const float4*)w1, r1b = *(const float4*)(w1 + 4);
            unsigned hh[8];
            hh[0] = pack_h2(r0a.x, r1a.x); hh[1] = pack_h2(r0a.y, r1a.y);
            hh[2] = pack_h2(r0a.z, r1a.z); hh[3] = pack_h2(r0a.w, r1a.w);
            hh[4] = pack_h2(r0b.x, r1b.x); hh[5] = pack_h2(r0b.y, r1b.y);
            hh[6] = pack_h2(r0b.z, r1b.z); hh[7] = pack_h2(r0b.w, r1b.w);
            int base = bkp * 72 + bn8;
            *(uint4*)&Bh[base]     = make_uint4(hh[0], hh[1], hh[2], hh[3]);
            *(uint4*)&Bh[base + 4] = make_uint4(hh[4], hh[5], hh[6], hh[7]);
        }
        __syncthreads();
#pragma unroll
        for (int kk = 0; kk < 2; kk++) {
            int kp = kk * 8 + p;
            unsigned ah[4], bh[8][2];
            int r0 = (wid * 16 + q) * 20;
            int r8 = r0 + 160;
            ah[0] = Ah[r0 + kp];     ah[1] = Ah[r8 + kp];
            ah[2] = Ah[r0 + kp + 4]; ah[3] = Ah[r8 + kp + 4];
#pragma unroll
            for (int j = 0; j < 8; j++) {
                int n = j * 8 + q;
                bh[j][0] = Bh[kp * 72 + n]; bh[j][1] = Bh[(kp + 4) * 72 + n];
            }
#pragma unroll
            for (int j = 0; j < 8; j++) mma_fp16(c[j], ah, bh[j]);
        }
        __syncthreads();
    }

    float ssum[2] = {}, dsum[2] = {};
#pragma unroll
    for (int rb = 0; rb < 2; rb++) {
        int r = m0 + wid * 16 + q + rb * 8;
        bool ok = r < NN;
#pragma unroll
        for (int j = 0; j < 8; j++) {
            int cw = j * 8 + 2 * p;
            float v0 = c[j][rb * 2 + 0];
            float v1 = c[j][rb * 2 + 1];
            ssum[rb] += v0 * atts[cw] + v1 * atts[cw + 1];
            dsum[rb] += v0 * attd[cw] + v1 * attd[cw + 1];
            if (ok) ((__half2*)g_xp2h)[((long)r * 64 + cw) >> 1] = __floats2half2_rn(v0, v1);
        }
    }
#pragma unroll
    for (int rb = 0; rb < 2; rb++) {
        float s = ssum[rb], d = dsum[rb];
        s += __shfl_xor_sync(0xFFFFFFFFu, s, 1);
        s += __shfl_xor_sync(0xFFFFFFFFu, s, 2);
        d += __shfl_xor_sync(0xFFFFFFFFu, d, 1);
        d += __shfl_xor_sync(0xFFFFFFFFu, d, 2);
        if (p == 0) {
            int r = m0 + wid * 16 + q + rb * 8;
            if (r < NN) { g_asrc2[r] = s; g_adst2[r] = d; }
        }
    }
    PDL_LAUNCH();
}

// ---------------- layer-2: fused softmax + aggregation + pooling (warp/node) ----------------
__global__ __launch_bounds__(256) void k_agg2(const float* __restrict__ b2,
                                              float* __restrict__ out) {
    int w = (blockIdx.x * blockDim.x + threadIdx.x) >> 5;
    int lane = threadIdx.x & 31;
    PDL_WAIT();
    if (w >= NN) return;
    int s0 = g_row[w], e0 = g_row[w + 1];
    // --- softmax (max-free; logits bounded) across lanes, up to 96 edges ---
    float ad = g_adst2[w];
    float att_l[3];
    float den = 0.f;
#pragma unroll
    for (int it = 0; it < 3; it++) {
        int j = s0 + it * 32 + lane;
        float ex = 0.f;
        if (j < e0) {
            uint4 ej = g_edge[j];
            float a = g_asrc2[(int)ej.x] + ad + __uint_as_float(ej.y);
            a = a >= 0.f ? a : 0.2f * a;
            ex = __expf(a);
        }
        att_l[it] = ex;
        den += ex;
    }
    for (int o = 16; o; o >>= 1) den += __shfl_xor_sync(0xFFFFFFFFu, den, o);
    float rd = 1.f / (den + 1e-16f);
    // --- gather: 4 edge-slots x 8 lanes ---
    int g8 = lane >> 3, sl = lane & 7;
    float acc[8] = {};
    const uint4* X = (const uint4*)g_xp2h; // row = 8 uint4 (64 halfs)
    for (int base = s0; base < e0; base += 4) {
        int j = base + g8;
        int rel = j - s0;
        int src = (j < e0) ? (int)g_edge[j].x : 0;
        float a0 = __shfl_sync(0xFFFFFFFFu, att_l[0], rel & 31);
        float a1 = __shfl_sync(0xFFFFFFFFu, att_l[1], rel & 31);
        float a2 = __shfl_sync(0xFFFFFFFFu, att_l[2], rel & 31);
        if (j < e0) {
            float a = (rel < 32) ? a0 : ((rel < 64) ? a1 : a2);
            uint4 hv = X[(long)src * 8 + sl];
            float2 f0 = __half22float2(*(__half2*)&hv.x);
            float2 f1 = __half22float2(*(__half2*)&hv.y);
            float2 f2 = __half22float2(*(__half2*)&hv.z);
            float2 f3 = __half22float2(*(__half2*)&hv.w);
            acc[0] += f0.x * a; acc[1] += f0.y * a; acc[2] += f1.x * a; acc[3] += f1.y * a;
            acc[4] += f2.x * a; acc[5] += f2.y * a; acc[6] += f3.x * a; acc[7] += f3.y * a;
        }
    }
#pragma unroll
    for (int k = 0; k < 8; k++) {
        acc[k] += __shfl_xor_sync(0xFFFFFFFFu, acc[k], 8);
        acc[k] += __shfl_xor_sync(0xFFFFFFFFu, acc[k], 16);
    }
    if (lane < 8) {
        float4 ba = *(const float4*)(b2 + sl * 8);
        float4 bc = *(const float4*)(b2 + sl * 8 + 4);
        int g = w / NPG;
        float t = g_tag[w];
        float sc = g_scnt[g];
        float wgt = (t > 0.5f) ? (1.f / fmaxf(sc, 1.f)) : (1.f / fmaxf((float)NPG - sc, 1.f));
        int off = g * 128 + (t > 0.5f ? 64 : 0) + sl * 8;
        float4 o1 = make_float4((acc[0] * rd + ba.x) * wgt, (acc[1] * rd + ba.y) * wgt,
                                (acc[2] * rd + ba.z) * wgt, (acc[3] * rd + ba.w) * wgt);
        float4 o2 = make_float4((acc[4] * rd + bc.x) * wgt, (acc[5] * rd + bc.y) * wgt,
                                (acc[6] * rd + bc.z) * wgt, (acc[7] * rd + bc.w) * wgt);
        atomicAdd((float4*)(out + off), o1);
        atomicAdd((float4*)(out + off + 4), o2);
    }
}

// ---------------- PDL launch helper ----------------
static inline void pdl_launch(const void* fn, dim3 gd, dim3 bd, void** args) {
    cudaLaunchConfig_t cfg = {};
    cfg.gridDim = gd;
    cfg.blockDim = bd;
    cfg.dynamicSmemBytes = 0;
    cfg.stream = 0;
    cudaLaunchAttribute at;
    at.id = cudaLaunchAttributeProgrammaticStreamSerialization;
    at.val.programmaticStreamSerializationAllowed = 1;
    cfg.attrs = &at;
    cfg.numAttrs = 1;
    cudaLaunchKernelExC(&cfg, fn, args);
}

// ---------------- launch ----------------
extern "C" void kernel_launch(void* const* d_in, const int* in_sizes, int n_in,
                              void* d_out, int out_size) {
    const float* nf    = (const float*)d_in[0];
    const int*   ei    = (const int*)d_in[1];
    const float* ea    = (const float*)d_in[2];
    const int*   pm    = (const int*)d_in[3];
    const float* W1    = (const float*)d_in[4];
    const float* We1   = (const float*)d_in[5];
    const float* atts1 = (const float*)d_in[6];
    const float* attd1 = (const float*)d_in[7];
    const float* atte1 = (const float*)d_in[8];
    const float* b1    = (const float*)d_in[9];
    const float* W2    = (const float*)d_in[10];
    const float* We2   = (const float*)d_in[11];
    const float* atts2 = (const float*)d_in[12];
    const float* attd2 = (const float*)d_in[13];
    const float* atte2 = (const float*)d_in[14];
    const float* b2    = (const float*)d_in[15];
    float* out = (float*)d_out;

    k_prep<<<PREP_BLOCKS, 256>>>(pm, ei, ea, out);
    {
        void* a[] = {(void*)&We1, (void*)&atte1, (void*)&We2, (void*)&atte2};
        pdl_launch((const void*)k_scan1, dim3(99), dim3(512), a);
    }
    {
        void* a[] = {};
        pdl_launch((const void*)k_scan3, dim3((NN + 1 + 255) / 256), dim3(256), a);
    }
    {
        void* a[] = {(void*)&nf, (void*)&W1, (void*)&atts1, (void*)&attd1, (void*)&pm};
        pdl_launch((const void*)k_gemm1, dim3((NN + 127) / 128, 2), dim3(256), a);
    }
    {
        void* a[] = {(void*)&ei, (void*)&ea};
        pdl_launch((const void*)k_scatter, dim3((ET + 255) / 256), dim3(256), a);
    }
    {
        void* a[] = {(void*)&b1};
        pdl_launch((const void*)k_agg1, dim3((NN * 32 + 255) / 256), dim3(256), a);
    }
    {
        void* a[] = {(void*)&W2, (void*)&atts2, (void*)&attd2};
        pdl_launch((const void*)k_gemm2, dim3((NN + 127) / 128), dim3(256), a);
    }
    {
        void* a[] = {(void*)&b2, (void*)&out};
        pdl_launch((const void*)k_agg2, dim3((NN * 32 + 255) / 256), dim3(256), a);
    }
}

// round 17
// speedup vs baseline: 1.2378x; 1.0637x over previous
#include <cuda_runtime.h>
#include <cuda_fp16.h>

#define NN 50000
#define EE 400000
#define ET 450000   // EE + NN self loops
#define GG 1000
#define NPG 50
#define PREP_BLOCKS 1563

#define PDL_WAIT()   asm volatile("griddepcontrol.wait;" ::: "memory")
#define PDL_LAUNCH() asm volatile("griddepcontrol.launch_dependents;" ::: "memory")

// ---------------- static device scratch ----------------
static __device__ __align__(16) __half  g_xp1h[NN * 256];   // fp16 messages, layer 1
static __device__ __align__(16) __half  g_h1h[NN * 256];    // fp16 hidden, layer 1 out
static __device__ __align__(16) __half  g_xp2h[NN * 64];    // fp16 messages, layer 2
static __device__ __align__(16) unsigned g_nfA[NN * 64];    // fp16-pair node features
static __device__ __align__(16) unsigned g_W1p[64 * 256];   // W1 k-pair packed fp16
static __device__ __align__(16) unsigned g_W2p[128 * 64];   // W2 k-pair packed fp16
static __device__ __align__(16) float   g_asrc1[NN * 4];
// per-node record: [0..3] = adst1 (4 heads), [4..7] = den1 (4 heads) — one 32B sector
static __device__ __align__(32) float   g_nd1[NN * 8];
static __device__ float                 g_asrc2[NN];
static __device__ float                 g_adst2[NN];
static __device__ float                 g_tag[NN];
static __device__ float                 g_scnt[GG];         // solvent count per graph
// [0..3]=ue1, [4..7]=ve1, [8]=ue2, [9]=ve2, [10]=mean_ea0, [11]=mean_ea1
static __device__ float                 g_const[12];
// CSR by dst
static __device__ int                   g_cnt[NN];     // zero on entry; re-zeroed each run
static __device__ int                   g_row[NN + 1];
static __device__ int                   g_cur[NN];
static __device__ int                   g_part[128];
// packed per-edge payload: {src:int, ced:float, att01:half2, att23:half2}
static __device__ __align__(16) uint4   g_edge[ET];
static __device__ __align__(8) float2   g_eapart[PREP_BLOCKS];

// ---------------- fp16 helpers ----------------
__device__ __forceinline__ unsigned pack_h2(float lo, float hi) {
    __half2 h = __floats2half2_rn(lo, hi);
    return *(unsigned*)&h;
}
__device__ __forceinline__ void mma_fp16(float* c, const unsigned* a, const unsigned* b) {
    asm volatile(
        "mma.sync.aligned.m16n8k16.row.col.f32.f16.f16.f32 "
        "{%0,%1,%2,%3}, {%4,%5,%6,%7}, {%8,%9}, {%0,%1,%2,%3};"
        : "+f"(c[0]), "+f"(c[1]), "+f"(c[2]), "+f"(c[3])
        : "r"(a[0]), "r"(a[1]), "r"(a[2]), "r"(a[3]), "r"(b[0]), "r"(b[1]));
}

// ---------------- prep: histogram + tags + zeroing + ea sums + fp16 conversions ----------------
__global__ void k_prep(const int* __restrict__ pm, const int* __restrict__ EI,
                       const float* __restrict__ EA, const float* __restrict__ NF,
                       const float* __restrict__ W1, const float* __restrict__ W2,
                       float* __restrict__ out) {
    __shared__ float2 sred[8];
    int tid = threadIdx.x;
    int e = blockIdx.x * 256 + tid;
    float2 v = make_float2(0.f, 0.f);
    if (e < EE) {
        atomicAdd(&g_cnt[EI[EE + e]], 1);
        v = ((const float2*)EA)[e];
    }
    if (e < NN) g_tag[e] = (e == NN - 1 || pm[e + 1] != pm[e]) ? 1.f : 0.f;
    if (e < NN * 4) g_nd1[(e >> 2) * 8 + 4 + (e & 3)] = 0.f;   // zero den slots
    if (e < GG) g_scnt[e] = 0.f;
    if (e < GG * 128) out[e] = 0.f;
    // fp16 conversions (grid-stride)
    {
        int stride = PREP_BLOCKS * 256;
        const float2* nf2 = (const float2*)NF;
        for (int i = e; i < NN * 64; i += stride) {
            float2 p = nf2[i];
            g_nfA[i] = pack_h2(p.x, p.y);
        }
        for (int i = e; i < 64 * 256; i += stride) {
            int kp = i >> 8, n = i & 255;
            g_W1p[i] = pack_h2(W1[(2 * kp) * 256 + n], W1[(2 * kp + 1) * 256 + n]);
        }
        for (int i = e; i < 128 * 64; i += stride) {
            int kp = i >> 6, n = i & 63;
            g_W2p[i] = pack_h2(W2[(2 * kp) * 64 + n], W2[(2 * kp + 1) * 64 + n]);
        }
    }
    for (int o = 16; o; o >>= 1) {
        v.x += __shfl_xor_sync(0xFFFFFFFFu, v.x, o);
        v.y += __shfl_xor_sync(0xFFFFFFFFu, v.y, o);
    }
    if ((tid & 31) == 0) sred[tid >> 5] = v;
    __syncthreads();
    if (tid == 0) {
        float2 s = sred[0];
        for (int i = 1; i < 8; i++) { s.x += sred[i].x; s.y += sred[i].y; }
        g_eapart[blockIdx.x] = s;
    }
    PDL_LAUNCH();
}

// ---------------- scan1 (98 blocks) + const work (block 98) ----------------
__global__ void k_scan1(const float* __restrict__ We1, const float* __restrict__ atte1,
                        const float* __restrict__ We2, const float* __restrict__ atte2) {
    int t = threadIdx.x;
    PDL_WAIT();
    if (blockIdx.x == 98) {
        __shared__ float2 sred[16];
        if (t < 12) g_const[t] = 0.f;
        float2 v = make_float2(0.f, 0.f);
        for (int i = t; i < PREP_BLOCKS; i += 512) {
            float2 p = g_eapart[i];
            v.x += p.x; v.y += p.y;
        }
        for (int o = 16; o; o >>= 1) {
            v.x += __shfl_xor_sync(0xFFFFFFFFu, v.x, o);
            v.y += __shfl_xor_sync(0xFFFFFFFFu, v.y, o);
        }
        if ((t & 31) == 0) sred[t >> 5] = v;
        __syncthreads();
        if (t == 0) {
            float2 s = sred[0];
            for (int i = 1; i < 16; i++) { s.x += sred[i].x; s.y += sred[i].y; }
            g_const[10] = s.x * (1.f / EE);
            g_const[11] = s.y * (1.f / EE);
        }
        __syncthreads();
        if (t < 256) {
            int h = t >> 6;
            float a = atte1[t];
            atomicAdd(&g_const[h],     We1[t] * a);
            atomicAdd(&g_const[4 + h], We1[256 + t] * a);
            if (t < 64) {
                atomicAdd(&g_const[8], We2[t] * atte2[t]);
                atomicAdd(&g_const[9], We2[64 + t] * atte2[t]);
            }
        }
        PDL_LAUNCH();
        return;
    }
    __shared__ int sd[512];
    int i = blockIdx.x * 512 + t;
    int v = (i < NN) ? g_cnt[i] + 1 : 0;   // +1 self loop
    sd[t] = v; __syncthreads();
    for (int off = 1; off < 512; off <<= 1) {
        int x = (t >= off) ? sd[t - off] : 0;
        __syncthreads();
        sd[t] += x;
        __syncthreads();
    }
    if (i < NN) g_row[i + 1] = sd[t];
    if (t == 511) g_part[blockIdx.x] = sd[t];
    PDL_LAUNCH();
}

// ---------------- scan3: finalize row/cur, accumulate solvent counts ----------------
__global__ void k_scan3() {
    __shared__ int sp[98];
    int t = threadIdx.x;                   // 256
    PDL_WAIT();
    if (t < 98) sp[t] = g_part[t];
    __syncthreads();
    if (t == 0) {
        int run = 0;
        for (int i = 0; i < 98; i++) { int x = sp[i]; sp[i] = run; run += x; }
    }
    __syncthreads();
    int j = blockIdx.x * 256 + t;
    if (j <= NN) {
        int fr = (j == 0) ? 0 : (g_row[j] + sp[(j - 1) >> 9]);
        g_row[j] = fr;
        if (j < NN) {
            g_cur[j] = fr; g_cnt[j] = 0;   // re-zero cnt for next call
            float tg = g_tag[j];
            if (tg != 0.f) atomicAdd(&g_scnt[j / NPG], tg);
        }
    }
    PDL_LAUNCH();
}

// ---------------- GEMM1 (fp16 MMA, preconverted operands, reg-prefetch) ----------------
__global__ __launch_bounds__(256) void k_gemm1(const float* __restrict__ W,
                                               const float* __restrict__ atts,
                                               const float* __restrict__ attd,
                                               const int* __restrict__ pm) {
    __shared__ unsigned Ah[128 * 20];      // k-pairs, pitch 20
    __shared__ unsigned Bh[16 * 136];      // k-pair rows x n, pitch 136
    int tid = threadIdx.x;
    int wid = tid >> 5, lane = tid & 31;
    int warp_m = wid & 3, warp_n = wid >> 2;
    int q = lane >> 2, p = lane & 3;
    int m0 = blockIdx.x * 128, n0 = blockIdx.y * 128;
    float c[2][8][4];
#pragma unroll
    for (int i = 0; i < 2; i++)
#pragma unroll
        for (int j = 0; j < 8; j++)
#pragma unroll
            for (int k = 0; k < 4; k++) c[i][j][k] = 0.f;

    int arow = tid >> 1, ahalf8 = (tid & 1) * 8;   // uint offset (8 uints = 16 halfs)
    int bkp = tid >> 4, bn8 = (tid & 15) * 8;
    bool aok = (m0 + arow) < NN;
    long abase = (long)(m0 + arow) * 64 + ahalf8;
    int bbase = bkp * 256 + n0 + bn8;
    uint4 z = make_uint4(0u, 0u, 0u, 0u);

    uint4 pa0 = aok ? *(const uint4*)(g_nfA + abase) : z;
    uint4 pa1 = aok ? *(const uint4*)(g_nfA + abase + 4) : z;
    uint4 pb0 = *(const uint4*)(g_W1p + bbase);
    uint4 pb1 = *(const uint4*)(g_W1p + bbase + 4);

    for (int k0 = 0; k0 < 128; k0 += 32) {
        int abse = arow * 20 + ahalf8;
        *(uint4*)&Ah[abse]     = pa0;
        *(uint4*)&Ah[abse + 4] = pa1;
        int bbse = bkp * 136 + bn8;
        *(uint4*)&Bh[bbse]     = pb0;
        *(uint4*)&Bh[bbse + 4] = pb1;
        __syncthreads();
        if (k0 < 96) {
            long an = abase + (k0 + 32) / 2;
            pa0 = aok ? *(const uint4*)(g_nfA + an) : z;
            pa1 = aok ? *(const uint4*)(g_nfA + an + 4) : z;
            int bn = bbase + ((k0 + 32) / 2) * 256;
            pb0 = *(const uint4*)(g_W1p + bn);
            pb1 = *(const uint4*)(g_W1p + bn + 4);
        }
#pragma unroll
        for (int kk = 0; kk < 2; kk++) {
            int kp = kk * 8 + p;
            unsigned ah[2][4], bh[8][2];
#pragma unroll
            for (int i = 0; i < 2; i++) {
                int r0 = (warp_m * 32 + i * 16 + q) * 20;
                int r8 = r0 + 160;
                ah[i][0] = Ah[r0 + kp];     ah[i][1] = Ah[r8 + kp];
                ah[i][2] = Ah[r0 + kp + 4]; ah[i][3] = Ah[r8 + kp + 4];
            }
#pragma unroll
            for (int j = 0; j < 8; j++) {
                int n = warp_n * 64 + j * 8 + q;
                bh[j][0] = Bh[kp * 136 + n]; bh[j][1] = Bh[(kp + 4) * 136 + n];
            }
#pragma unroll
            for (int i = 0; i < 2; i++)
#pragma unroll
                for (int j = 0; j < 8; j++) mma_fp16(c[i][j], ah[i], bh[j]);
        }
        __syncthreads();
    }

    int head = blockIdx.y * 2 + warp_n;
    const float* asv = atts + head * 64;
    const float* adv = attd + head * 64;
    float ssum[2][2] = {}, dsum[2][2] = {};
#pragma unroll
    for (int i = 0; i < 2; i++) {
#pragma unroll
        for (int rb = 0; rb < 2; rb++) {
            int r = m0 + warp_m * 32 + i * 16 + q + rb * 8;
            bool ok = r < NN;
            float tg = ok ? ((r == NN - 1 || pm[r + 1] != pm[r]) ? 1.f : 0.f) : 0.f;
#pragma unroll
            for (int j = 0; j < 8; j++) {
                int cw = j * 8 + 2 * p;
                int col = n0 + warp_n * 64 + cw;
                float w0 = W[128 * 256 + col];
                float w1 = W[128 * 256 + col + 1];
                float v0 = c[i][j][rb * 2 + 0] + tg * w0;
                float v1 = c[i][j][rb * 2 + 1] + tg * w1;
                ssum[i][rb] += v0 * asv[cw] + v1 * asv[cw + 1];
                dsum[i][rb] += v0 * adv[cw] + v1 * adv[cw + 1];
                if (ok) ((__half2*)g_xp1h)[((long)r * 256 + col) >> 1] = __floats2half2_rn(v0, v1);
            }
        }
    }
#pragma unroll
    for (int i = 0; i < 2; i++)
#pragma unroll
        for (int rb = 0; rb < 2; rb++) {
            float s = ssum[i][rb], d = dsum[i][rb];
            s += __shfl_xor_sync(0xFFFFFFFFu, s, 1);
            s += __shfl_xor_sync(0xFFFFFFFFu, s, 2);
            d += __shfl_xor_sync(0xFFFFFFFFu, d, 1);
            d += __shfl_xor_sync(0xFFFFFFFFu, d, 2);
            if (p == 0) {
                int r = m0 + warp_m * 32 + i * 16 + q + rb * 8;
                if (r < NN) { g_asrc1[r * 4 + head] = s; g_nd1[r * 8 + head] = d; }
            }
        }
    PDL_LAUNCH();
}

// ---------------- scatter + fused layer-1 attention (packed 16B edge payload) ----------------
__global__ void k_scatter(const int* __restrict__ EI, const float* __restrict__ EA) {
    int e = blockIdx.x * blockDim.x + threadIdx.x;
    int s = 0, d = 0; float2 ea = make_float2(0.f, 0.f);
    bool real = e < EE;
    if (real) {
        s = EI[e]; d = EI[EE + e];
        ea = ((const float2*)EA)[e];
    }
    PDL_WAIT();
    if (e >= ET) { PDL_LAUNCH(); return; }
    if (!real) {
        s = d = e - EE;
        ea.x = g_const[10]; ea.y = g_const[11];
    }
    int pos = atomicAdd(&g_cur[d], 1);
    float ced = ea.x * g_const[8] + ea.y * g_const[9];     // layer-2 edge logit term
    float4 as = *(const float4*)(g_asrc1 + s * 4);
    float4 ad = *(const float4*)(g_nd1 + d * 8);
    float a0 = as.x + ad.x + ea.x * g_const[0] + ea.y * g_const[4]; a0 = a0 >= 0.f ? a0 : 0.2f * a0;
    float a1 = as.y + ad.y + ea.x * g_const[1] + ea.y * g_const[5]; a1 = a1 >= 0.f ? a1 : 0.2f * a1;
    float a2 = as.z + ad.z + ea.x * g_const[2] + ea.y * g_const[6]; a2 = a2 >= 0.f ? a2 : 0.2f * a2;
    float a3 = as.w + ad.w + ea.x * g_const[3] + ea.y * g_const[7]; a3 = a3 >= 0.f ? a3 : 0.2f * a3;
    __half2 e01 = __floats2half2_rn(__expf(a0), __expf(a1));
    __half2 e23 = __floats2half2_rn(__expf(a2), __expf(a3));
    g_edge[pos] = make_uint4((unsigned)s, __float_as_uint(ced),
                             *(unsigned*)&e01, *(unsigned*)&e23);
    // den accumulates the fp16-rounded exps so each softmax still sums to exactly 1
    float2 r01 = __half22float2(e01), r23 = __half22float2(e23);
    atomicAdd((float4*)(g_nd1 + d * 8 + 4), make_float4(r01.x, r01.y, r23.x, r23.y));
    PDL_LAUNCH();
}

// ---------------- layer-1 aggregation: 1 warp/node, fp16 in/out, 2 edges/iter ----------------
__global__ __launch_bounds__(256) void k_agg1(const float* __restrict__ b1) {
    int w = (blockIdx.x * blockDim.x + threadIdx.x) >> 5;
    int lane = threadIdx.x & 31;
    PDL_WAIT();
    if (w >= NN) { PDL_LAUNCH(); return; }
    int s0 = g_row[w], e0 = g_row[w + 1];
    int head = lane >> 3;                  // 8 lanes per head
    float acc[8] = {};
    const uint4* X = (const uint4*)g_xp1h; // row = 32 uint4 (256 halfs)
    int j = s0;
    for (; j + 2 <= e0; j += 2) {
        uint4 eA = g_edge[j], eB = g_edge[j + 1];              // uniform
        uint4 hvA = X[(long)(int)eA.x * 32 + lane];
        uint4 hvB = X[(long)(int)eB.x * 32 + lane];
        float2 lA = __half22float2(*(__half2*)&eA.z), hA = __half22float2(*(__half2*)&eA.w);
        float2 lB = __half22float2(*(__half2*)&eB.z), hB = __half22float2(*(__half2*)&eB.w);
        float aA = head == 0 ? lA.x : head == 1 ? lA.y : head == 2 ? hA.x : hA.y;
        float aB = head == 0 ? lB.x : head == 1 ? lB.y : head == 2 ? hB.x : hB.y;
        float2 f;
        f = __half22float2(*(__half2*)&hvA.x); acc[0] += f.x * aA; acc[1] += f.y * aA;
        f = __half22float2(*(__half2*)&hvA.y); acc[2] += f.x * aA; acc[3] += f.y * aA;
        f = __half22float2(*(__half2*)&hvA.z); acc[4] += f.x * aA; acc[5] += f.y * aA;
        f = __half22float2(*(__half2*)&hvA.w); acc[6] += f.x * aA; acc[7] += f.y * aA;
        f = __half22float2(*(__half2*)&hvB.x); acc[0] += f.x * aB; acc[1] += f.y * aB;
        f = __half22float2(*(__half2*)&hvB.y); acc[2] += f.x * aB; acc[3] += f.y * aB;
        f = __half22float2(*(__half2*)&hvB.z); acc[4] += f.x * aB; acc[5] += f.y * aB;
        f = __half22float2(*(__half2*)&hvB.w); acc[6] += f.x * aB; acc[7] += f.y * aB;
    }
    if (j < e0) {
        uint4 eA = g_edge[j];
        uint4 hv = X[(long)(int)eA.x * 32 + lane];
        float2 lA = __half22float2(*(__half2*)&eA.z), hA = __half22float2(*(__half2*)&eA.w);
        float a = head == 0 ? lA.x : head == 1 ? lA.y : head == 2 ? hA.x : hA.y;
        float2 f;
        f = __half22float2(*(__half2*)&hv.x); acc[0] += f.x * a; acc[1] += f.y * a;
        f = __half22float2(*(__half2*)&hv.y); acc[2] += f.x * a; acc[3] += f.y * a;
        f = __half22float2(*(__half2*)&hv.z); acc[4] += f.x * a; acc[5] += f.y * a;
        f = __half22float2(*(__half2*)&hv.w); acc[6] += f.x * a; acc[7] += f.y * a;
    }
    float4 dv = *(const float4*)(g_nd1 + w * 8 + 4);
    float den = head == 0 ? dv.x : head == 1 ? dv.y : head == 2 ? dv.z : dv.w;
    float rd = 1.f / (den + 1e-16f);
    float4 ba = *(const float4*)(b1 + lane * 8);
    float4 bc = *(const float4*)(b1 + lane * 8 + 4);
    float o0 = fmaxf(acc[0] * rd + ba.x, 0.f), o1 = fmaxf(acc[1] * rd + ba.y, 0.f);
    float o2 = fmaxf(acc[2] * rd + ba.z, 0.f), o3 = fmaxf(acc[3] * rd + ba.w, 0.f);
    float o4 = fmaxf(acc[4] * rd + bc.x, 0.f), o5 = fmaxf(acc[5] * rd + bc.y, 0.f);
    float o6 = fmaxf(acc[6] * rd + bc.z, 0.f), o7 = fmaxf(acc[7] * rd + bc.w, 0.f);
    __half2 p0 = __floats2half2_rn(o0, o1), p1 = __floats2half2_rn(o2, o3);
    __half2 p2 = __floats2half2_rn(o4, o5), p3 = __floats2half2_rn(o6, o7);
    uint4 pk = make_uint4(*(unsigned*)&p0, *(unsigned*)&p1, *(unsigned*)&p2, *(unsigned*)&p3);
    *(uint4*)&g_h1h[(long)w * 256 + lane * 8] = pk;
    PDL_LAUNCH();
}

// ---------------- GEMM2 (fp16 MMA, preconverted W2, reg-prefetch) ----------------
__global__ __launch_bounds__(256) void k_gemm2(const float* __restrict__ atts,
                                               const float* __restrict__ attd) {
    __shared__ unsigned Ah[128 * 20];
    __shared__ unsigned Bh[16 * 72];
    int tid = threadIdx.x;
    int wid = tid >> 5, lane = tid & 31;
    int q = lane >> 2, p = lane & 3;
    int m0 = blockIdx.x * 128;
    float c[8][4];
#pragma unroll
    for (int j = 0; j < 8; j++)
#pragma unroll
        for (int k = 0; k < 4; k++) c[j][k] = 0.f;

    int arow = tid >> 1, ahalf8 = (tid & 1) * 8;
    int bkp = tid >> 3, bn8 = (tid & 7) * 8;       // tid<128 loads B
    bool aok = (m0 + arow) < NN;
    const __half* abase = g_h1h + (long)(m0 + arow) * 256 + ahalf8 * 2;
    int bbase = bkp * 64 + bn8;
    uint4 z = make_uint4(0u, 0u, 0u, 0u);
    PDL_WAIT();

    uint4 pa0 = aok ? *(const uint4*)abase : z;
    uint4 pa1 = aok ? *(const uint4*)(abase + 8) : z;
    uint4 pb0 = z, pb1 = z;
    if (tid < 128) {
        pb0 = *(const uint4*)(g_W2p + bbase);
        pb1 = *(const uint4*)(g_W2p + bbase + 4);
    }

    for (int k0 = 0; k0 < 256; k0 += 32) {
        int abse = arow * 20 + ahalf8;
        *(uint4*)&Ah[abse]     = pa0;
        *(uint4*)&Ah[abse + 4] = pa1;
        if (tid < 128) {
            int bbse = bkp * 72 + bn8;
            *(uint4*)&Bh[bbse]     = pb0;
            *(uint4*)&Bh[bbse + 4] = pb1;
        }
        __syncthreads();
        if (k0 < 224) {
            const __half* an = abase + (k0 + 32);
            pa0 = aok ? *(const uint4*)an : z;
            pa1 = aok ? *(const uint4*)(an + 8) : z;
            if (tid < 128) {
                int bn = bbase + ((k0 + 32) / 2) * 64;
                pb0 = *(const uint4*)(g_W2p + bn);
                pb1 = *(const uint4*)(g_W2p + bn + 4);
            }
        }
#pragma unroll
        for (int kk = 0; kk < 2; kk++) {
            int kp = kk * 8 + p;
            unsigned ah[4], bh[8][2];
            int r0 = (wid * 16 + q) * 20;
            int r8 = r0 + 160;
            ah[0] = Ah[r0 + kp];     ah[1] = Ah[r8 + kp];
            ah[2] = Ah[r0 + kp + 4]; ah[3] = Ah[r8 + kp + 4];
#pragma unroll
            for (int j = 0; j < 8; j++) {
                int n = j * 8 + q;
                bh[j][0] = Bh[kp * 72 + n]; bh[j][1] = Bh[(kp + 4) * 72 + n];
            }
#pragma unroll
            for (int j = 0; j < 8; j++) mma_fp16(c[j], ah, bh[j]);
        }
        __syncthreads();
    }

    float ssum[2] = {}, dsum[2] = {};
#pragma unroll
    for (int rb = 0; rb < 2; rb++) {
        int r = m0 + wid * 16 + q + rb * 8;
        bool ok = r < NN;
#pragma unroll
        for (int j = 0; j < 8; j++) {
            int cw = j * 8 + 2 * p;
            float v0 = c[j][rb * 2 + 0];
            float v1 = c[j][rb * 2 + 1];
            ssum[rb] += v0 * atts[cw] + v1 * atts[cw + 1];
            dsum[rb] += v0 * attd[cw] + v1 * attd[cw + 1];
            if (ok) ((__half2*)g_xp2h)[((long)r * 64 + cw) >> 1] = __floats2half2_rn(v0, v1);
        }
    }
#pragma unroll
    for (int rb = 0; rb < 2; rb++) {
        float s = ssum[rb], d = dsum[rb];
        s += __shfl_xor_sync(0xFFFFFFFFu, s, 1);
        s += __shfl_xor_sync(0xFFFFFFFFu, s, 2);
        d += __shfl_xor_sync(0xFFFFFFFFu, d, 1);
        d += __shfl_xor_sync(0xFFFFFFFFu, d, 2);
        if (p == 0) {
            int r = m0 + wid * 16 + q + rb * 8;
            if (r < NN) { g_asrc2[r] = s; g_adst2[r] = d; }
        }
    }
    PDL_LAUNCH();
}

// ---------------- layer-2: fused softmax + aggregation + pooling (warp/node) ----------------
__global__ __launch_bounds__(256) void k_agg2(const float* __restrict__ b2,
                                              float* __restrict__ out) {
    int w = (blockIdx.x * blockDim.x + threadIdx.x) >> 5;
    int lane = threadIdx.x & 31;
    PDL_WAIT();
    if (w >= NN) return;
    int s0 = g_row[w], e0 = g_row[w + 1];
    // --- softmax (max-free; logits bounded) across lanes, up to 96 edges ---
    float ad = g_adst2[w];
    float att_l[3];
    float den = 0.f;
#pragma unroll
    for (int it = 0; it < 3; it++) {
        int j = s0 + it * 32 + lane;
        float ex = 0.f;
        if (j < e0) {
            uint4 ej = g_edge[j];
            float a = g_asrc2[(int)ej.x] + ad + __uint_as_float(ej.y);
            a = a >= 0.f ? a : 0.2f * a;
            ex = __expf(a);
        }
        att_l[it] = ex;
        den += ex;
    }
    for (int o = 16; o; o >>= 1) den += __shfl_xor_sync(0xFFFFFFFFu, den, o);
    float rd = 1.f / (den + 1e-16f);
    // --- gather: 4 edge-slots x 8 lanes ---
    int g8 = lane >> 3, sl = lane & 7;
    float acc[8] = {};
    const uint4* X = (const uint4*)g_xp2h; // row = 8 uint4 (64 halfs)
    for (int base = s0; base < e0; base += 4) {
        int j = base + g8;
        int rel = j - s0;
        int src = (j < e0) ? (int)g_edge[j].x : 0;
        float a0 = __shfl_sync(0xFFFFFFFFu, att_l[0], rel & 31);
        float a1 = __shfl_sync(0xFFFFFFFFu, att_l[1], rel & 31);
        float a2 = __shfl_sync(0xFFFFFFFFu, att_l[2], rel & 31);
        if (j < e0) {
            float a = (rel < 32) ? a0 : ((rel < 64) ? a1 : a2);
            uint4 hv = X[(long)src * 8 + sl];
            float2 f0 = __half22float2(*(__half2*)&hv.x);
            float2 f1 = __half22float2(*(__half2*)&hv.y);
            float2 f2 = __half22float2(*(__half2*)&hv.z);
            float2 f3 = __half22float2(*(__half2*)&hv.w);
            acc[0] += f0.x * a; acc[1] += f0.y * a; acc[2] += f1.x * a; acc[3] += f1.y * a;
            acc[4] += f2.x * a; acc[5] += f2.y * a; acc[6] += f3.x * a; acc[7] += f3.y * a;
        }
    }
#pragma unroll
    for (int k = 0; k < 8; k++) {
        acc[k] += __shfl_xor_sync(0xFFFFFFFFu, acc[k], 8);
        acc[k] += __shfl_xor_sync(0xFFFFFFFFu, acc[k], 16);
    }
    if (lane < 8) {
        float4 ba = *(const float4*)(b2 + sl * 8);
        float4 bc = *(const float4*)(b2 + sl * 8 + 4);
        int g = w / NPG;
        float t = g_tag[w];
        float sc = g_scnt[g];
        float wgt = (t > 0.5f) ? (1.f / fmaxf(sc, 1.f)) : (1.f / fmaxf((float)NPG - sc, 1.f));
        int off = g * 128 + (t > 0.5f ? 64 : 0) + sl * 8;
        float4 o1 = make_float4((acc[0] * rd + ba.x) * wgt, (acc[1] * rd + ba.y) * wgt,
                                (acc[2] * rd + ba.z) * wgt, (acc[3] * rd + ba.w) * wgt);
        float4 o2 = make_float4((acc[4] * rd + bc.x) * wgt, (acc[5] * rd + bc.y) * wgt,
                                (acc[6] * rd + bc.z) * wgt, (acc[7] * rd + bc.w) * wgt);
        atomicAdd((float4*)(out + off), o1);
        atomicAdd((float4*)(out + off + 4), o2);
    }
}

// ---------------- PDL launch helper ----------------
static inline void pdl_launch(const void* fn, dim3 gd, dim3 bd, void** args) {
    cudaLaunchConfig_t cfg = {};
    cfg.gridDim = gd;
    cfg.blockDim = bd;
    cfg.dynamicSmemBytes = 0;
    cfg.stream = 0;
    cudaLaunchAttribute at;
    at.id = cudaLaunchAttributeProgrammaticStreamSerialization;
    at.val.programmaticStreamSerializationAllowed = 1;
    cfg.attrs = &at;
    cfg.numAttrs = 1;
    cudaLaunchKernelExC(&cfg, fn, args);
}

// ---------------- launch ----------------
extern "C" void kernel_launch(void* const* d_in, const int* in_sizes, int n_in,
                              void* d_out, int out_size) {
    const float* nf    = (const float*)d_in[0];
    const int*   ei    = (const int*)d_in[1];
    const float* ea    = (const float*)d_in[2];
    const int*   pm    = (const int*)d_in[3];
    const float* W1    = (const float*)d_in[4];
    const float* We1   = (const float*)d_in[5];
    const float* atts1 = (const float*)d_in[6];
    const float* attd1 = (const float*)d_in[7];
    const float* atte1 = (const float*)d_in[8];
    const float* b1    = (const float*)d_in[9];
    const float* W2    = (const float*)d_in[10];
    const float* We2   = (const float*)d_in[11];
    const float* atts2 = (const float*)d_in[12];
    const float* attd2 = (const float*)d_in[13];
    const float* atte2 = (const float*)d_in[14];
    const float* b2    = (const float*)d_in[15];
    float* out = (float*)d_out;

    k_prep<<<PREP_BLOCKS, 256>>>(pm, ei, ea, nf, W1, W2, out);
    {
        void* a[] = {(void*)&We1, (void*)&atte1, (void*)&We2, (void*)&atte2};
        pdl_launch((const void*)k_scan1, dim3(99), dim3(512), a);
    }
    {
        void* a[] = {};
        pdl_launch((const void*)k_scan3, dim3((NN + 1 + 255) / 256), dim3(256), a);
    }
    {
        void* a[] = {(void*)&W1, (void*)&atts1, (void*)&attd1, (void*)&pm};
        pdl_launch((const void*)k_gemm1, dim3((NN + 127) / 128, 2), dim3(256), a);
    }
    {
        void* a[] = {(void*)&ei, (void*)&ea};
        pdl_launch((const void*)k_scatter, dim3((ET + 255) / 256), dim3(256), a);
    }
    {
        void* a[] = {(void*)&b1};
        pdl_launch((const void*)k_agg1, dim3((NN * 32 + 255) / 256), dim3(256), a);
    }
    {
        void* a[] = {(void*)&atts2, (void*)&attd2};
        pdl_launch((const void*)k_gemm2, dim3((NN + 127) / 128), dim3(256), a);
    }
    {
        void* a[] = {(void*)&b2, (void*)&out};
        pdl_launch((const void*)k_agg2, dim3((NN * 32 + 255) / 256), dim3(256), a);
    }
}